// round 15
// baseline (speedup 1.0000x reference)
#include <cuda_runtime.h>
#include <cuda_fp16.h>
#include <math.h>

#define Bc 4
#define Lc 32
#define Cc 32
#define Hc 128
#define Wc 128
#define HWc (Hc*Wc)
#define IMG_SLICE (Cc*HWc)          // fp32 elements per image slice (d_out)
#define IMG_SLICE_H (Cc*HWc)        // fp16 elements per internal slice
#define IMG_BLKS (HWc/64)           // 256 image blocks per (lp,b), 64 px each
#define FLOW_BLKS (HWc/256)         // 64 flow blocks per (lp,b)

// Internal image buffers, channel-interleaved [B,L,H,W,C], fp16 (uint4 aligned).
__device__ uint4 g_imgA4[(size_t)Bc*Lc*IMG_SLICE_H/8];   // transposed input + ping-pong
__device__ uint4 g_imgB4[(size_t)Bc*Lc*IMG_SLICE_H/8];   // ping-pong
__device__ uint4 g_imgF4[(size_t)Bc*Lc*IMG_SLICE_H/8];   // finalized gather sources
// Flow buffers, planar [B,L,2,H,W], fp32 (precision-critical: feeds coordinates)
__device__ float g_flowA[(size_t)Bc*Lc*2*HWc];
__device__ float g_flowB[(size_t)Bc*Lc*2*HWc];
__device__ float g_flowF[(size_t)Bc*Lc*2*HWc];

union H8 { uint4 u; __half2 h[4]; };

// ---------------------------------------------------------------------------
// CHW(fp32) -> HWC(fp16) transpose of all input image slices into g_imgA;
// also copies slice l==0 straight to d_out (CHW fp32) on the fly.
__global__ void t_chw2hwc(const float* __restrict__ src, float* __restrict__ out) {
    __shared__ float sm[32][65];
    int tile = blockIdx.x & 255;
    int sl   = blockIdx.x >> 8;
    int pix0 = tile * 64;
    const float* s = src + (size_t)sl * IMG_SLICE;
    __half*      d = (__half*)g_imgA4 + (size_t)sl * IMG_SLICE_H;
    float*       o = out + (size_t)sl * IMG_SLICE;
    bool isL0 = ((sl & (Lc - 1)) == 0);
    int tx = threadIdx.x & 63, ty = threadIdx.x >> 6;
    #pragma unroll
    for (int i = 0; i < 8; i++) {
        int c = ty + i * 4;
        float v = s[c * HWc + pix0 + tx];
        sm[c][tx] = v;
        if (isL0) o[c * HWc + pix0 + tx] = v;
    }
    __syncthreads();
    // each thread packs 8 channels of one pixel into a uint4 (8 halves)
    int p = threadIdx.x >> 2, q = threadIdx.x & 3;
    H8 v;
    #pragma unroll
    for (int j = 0; j < 4; j++)
        v.h[j] = __floats2half2_rn(sm[8*q + 2*j][p], sm[8*q + 2*j + 1][p]);
    *(uint4*)(d + (pix0 + p) * Cc + q * 8) = v.u;
}

// ---------------------------------------------------------------------------
// Grid/weight computation — VERBATIM the numerics that passed (R2/R5/R10/R11).
__device__ __forceinline__ void grid_weights(
    int pix, float qfx, float qfy,
    float& w00, float& w01, float& w10, float& w11,
    int& o00, int& o01, int& o10, int& o11)
{
    int h = pix >> 7;
    int w = pix & (Wc - 1);
    float gx = -1.0f + (2.0f / Wc) * ((float)w + 0.5f);
    float gy = -1.0f + (2.0f / Hc) * ((float)h + 0.5f);
    float fx = gx + qfx;
    float t  = fx + 1.0f;
    fx = t - 2.0f * floorf(t * 0.5f) - 1.0f;   // remainder(fx+1,2)-1 (x wrap)
    float fy = gy + qfy;

    float x = (fx + 1.0f) * (Wc * 0.5f) - 0.5f;
    float y = (fy + 1.0f) * (Hc * 0.5f) - 0.5f;
    float x0f = floorf(x), y0f = floorf(y);
    float tx = x - x0f, ty = y - y0f;
    int x0 = (int)x0f, y0 = (int)y0f;
    int x1 = x0 + 1,  y1 = y0 + 1;

    float vx0 = (x0 >= 0 && x0 < Wc) ? 1.0f : 0.0f;
    float vx1 = (x1 >= 0 && x1 < Wc) ? 1.0f : 0.0f;
    float vy0 = (y0 >= 0 && y0 < Hc) ? 1.0f : 0.0f;
    float vy1 = (y1 >= 0 && y1 < Hc) ? 1.0f : 0.0f;

    w00 = (1.0f - tx) * (1.0f - ty) * vx0 * vy0;
    w01 = tx * (1.0f - ty) * vx1 * vy0;
    w10 = (1.0f - tx) * ty * vx0 * vy1;
    w11 = tx * ty * vx1 * vy1;

    int cx0 = min(max(x0, 0), Wc - 1), cx1 = min(max(x1, 0), Wc - 1);
    int cy0 = min(max(y0, 0), Hc - 1), cy1 = min(max(y1, 0), Hc - 1);
    o00 = cy0 * Wc + cx0; o01 = cy0 * Wc + cx1;
    o10 = cy1 * Wc + cx0; o11 = cy1 * Wc + cx1;
}

// flowSel: 0 = runtime input flows, 1 = g_flowA, 2 = g_flowB
__device__ __forceinline__ const float* flow_sel(int sel, const float* flows) {
    return (sel == 0) ? flows : (sel == 1) ? (const float*)g_flowA : (const float*)g_flowB;
}

// ---------------------------------------------------------------------------
// Fused step kernel. Block-level specialization:
//   blockIdx.x <  IMG_BLKS : image compose (fp16 scratch, fp32 math)
//   blockIdx.x >= IMG_BLKS : flow compose (fp32, unchanged)
__global__ void __launch_bounds__(256) compose_step(int step, int finHWC,
    int imgPar, int flowSrcSel, int flowDstSel,
    const float* __restrict__ flows, float* __restrict__ outImg)
{
    int lp = blockIdx.y;
    int b  = blockIdx.z;
    int l  = step + lp;
    const float* srcFlow = flow_sel(flowSrcSel, flows);

    if (blockIdx.x >= IMG_BLKS) {
        // ---------------- flow path (fp32, verbatim R10/R11) ----------------
        int pix = (blockIdx.x - IMG_BLKS) * 256 + threadIdx.x;

        const float* cf = srcFlow + (b * Lc + l) * (2 * HWc);
        float qfx = __ldg(cf + pix);
        float qfy = __ldg(cf + HWc + pix);

        float w00, w01, w10, w11; int o00, o01, o10, o11;
        grid_weights(pix, qfx, qfy, w00, w01, w10, w11, o00, o01, o10, o11);

        const float* pf = (lp == 0) ? (flows + (b * Lc) * (2 * HWc))
                       : (lp < step) ? ((const float*)g_flowF + (b * Lc + lp) * (2 * HWc))
                                     : (srcFlow + (b * Lc + lp) * (2 * HWc));
        float* dstFlow = (flowDstSel == 1) ? g_flowA : g_flowB;
        float* df = ((l < 2 * step) ? g_flowF : dstFlow) + (b * Lc + l) * (2 * HWc);

        float s0 = w00 * __ldg(pf + o00) + w01 * __ldg(pf + o01)
                 + w10 * __ldg(pf + o10) + w11 * __ldg(pf + o11);
        const float* pf1 = pf + HWc;
        float s1 = w00 * __ldg(pf1 + o00) + w01 * __ldg(pf1 + o01)
                 + w10 * __ldg(pf1 + o10) + w11 * __ldg(pf1 + o11);
        df[pix]       = qfx + s0;
        df[HWc + pix] = qfy + s1;
        return;
    }

    // ---------------- image path: warp = 8 px x 4 groups (8ch fp16/lane) ---
    // Phase 1: threads 0..63 compute weights/offsets for the block's 64 px
    // into smW (kills the 4x per-lane duplication of grid_weights).
    // Phase 2: VERBATIM R11 gather/FMA/store body, weights from 6 LDS.
    __shared__ float smW[64 * 6];
    __shared__ float smO[64 * 33];
    int t = threadIdx.x;

    if (t < 64) {
        int pixw = blockIdx.x * 64 + t;
        const float* cfw = srcFlow + (b * Lc + l) * (2 * HWc);
        float qx = __ldg(cfw + pixw);
        float qy = __ldg(cfw + HWc + pixw);
        float u00, u01, u10, u11; int a00, a01, a10, a11;
        grid_weights(pixw, qx, qy, u00, u01, u10, u11, a00, a01, a10, a11);
        smW[t*6+0] = u00; smW[t*6+1] = u01; smW[t*6+2] = u10; smW[t*6+3] = u11;
        smW[t*6+4] = __uint_as_float((unsigned)a00 | ((unsigned)a01 << 16));
        smW[t*6+5] = __uint_as_float((unsigned)a10 | ((unsigned)a11 << 16));
    }
    __syncthreads();

    int c8  = t & 3;
    int pl  = t >> 2;                 // pixel-local 0..63
    int pix = blockIdx.x * 64 + pl;
    int co  = c8 * 8;                 // channel offset (halves)

    float w00 = smW[pl*6+0], w01 = smW[pl*6+1];
    float w10 = smW[pl*6+2], w11 = smW[pl*6+3];
    unsigned oa = __float_as_uint(smW[pl*6+4]);
    unsigned ob = __float_as_uint(smW[pl*6+5]);
    int o00 = (int)(oa & 0xffffu), o01 = (int)(oa >> 16);
    int o10 = (int)(ob & 0xffffu), o11 = (int)(ob >> 16);

    const __half* srcImg = (const __half*)(imgPar ? g_imgB4 : g_imgA4);
    __half*       dstImg = (__half*)(imgPar ? g_imgA4 : g_imgB4);

    const __half* pi = ((lp == 0) ? (const __half*)g_imgA4
                      : (lp < step) ? (const __half*)g_imgF4 : srcImg)
                       + (b * Lc + lp) * IMG_SLICE_H;
    H8 t00, t01, t10, t11, cv8;
    t00.u = *(const uint4*)(pi + o00 * Cc + co);
    t01.u = *(const uint4*)(pi + o01 * Cc + co);
    t10.u = *(const uint4*)(pi + o10 * Cc + co);
    t11.u = *(const uint4*)(pi + o11 * Cc + co);

    int hwcOff = (b * Lc + l) * IMG_SLICE_H + pix * Cc + co;
    cv8.u = *(const uint4*)(srcImg + hwcOff);

    float r[8];
    #pragma unroll
    for (int k = 0; k < 4; k++) {
        float2 c  = __half22float2(cv8.h[k]);
        float2 a0 = __half22float2(t00.h[k]);
        float2 a1 = __half22float2(t01.h[k]);
        float2 a2 = __half22float2(t10.h[k]);
        float2 a3 = __half22float2(t11.h[k]);
        r[2*k]   = c.x + w00 * a0.x + w01 * a1.x + w10 * a2.x + w11 * a3.x;
        r[2*k+1] = c.y + w00 * a0.y + w01 * a1.y + w10 * a2.y + w11 * a3.y;
    }

    if (l < 2 * step) {                         // finalized (block-uniform)
        if (finHWC) {
            H8 ov;
            #pragma unroll
            for (int k = 0; k < 4; k++)
                ov.h[k] = __floats2half2_rn(r[2*k], r[2*k+1]);
            *(uint4*)((__half*)g_imgF4 + hwcOff) = ov.u;
        }
        int sb = pl * 33 + co;
        #pragma unroll
        for (int i = 0; i < 8; i++) smO[sb + i] = r[i];
        __syncthreads();
        int lane = t & 31, wp = t >> 5;
        float* oC = outImg + (b * Lc + l) * IMG_SLICE + blockIdx.x * 64;
        #pragma unroll
        for (int i = 0; i < 4; i++) {
            int ch = wp * 4 + i;
            __stcs(oC + ch * HWc + lane,      smO[lane * 33 + ch]);
            __stcs(oC + ch * HWc + lane + 32, smO[(lane + 32) * 33 + ch]);
        }
    } else {
        H8 ov;
        #pragma unroll
        for (int k = 0; k < 4; k++)
            ov.h[k] = __floats2half2_rn(r[2*k], r[2*k+1]);
        *(uint4*)(dstImg + hwcOff) = ov.u;
    }
}

// ---------------------------------------------------------------------------
extern "C" void kernel_launch(void* const* d_in, const int* in_sizes, int n_in,
                              void* d_out, int out_size) {
    const float* flows  = (const float*)d_in[0];
    const float* images = (const float*)d_in[1];
    if (n_in >= 2 && in_sizes[0] > in_sizes[1]) {
        const float* tmp = flows; flows = images; images = tmp;
    }
    float* out = (float*)d_out;

    // 1) transpose input images CHW(fp32) -> HWC(fp16) into g_imgA (+ slice0 -> d_out)
    t_chw2hwc<<<Bc * Lc * 256, 256>>>(images, out);

    // 2) log-scan, one fused launch per step (image blocks + flow blocks).
    int imgPar = 0;
    int flowSrc = 0;
    for (int s = 1; s < Lc; s <<= 1) {
        int Lp = Lc - s;
        int flowDst = (flowSrc == 2) ? 1 : 2;
        int doFlow = (s < 16) ? 1 : 0;   // last step's flow output never consumed
        int finHWC = (s < 16) ? 1 : 0;   // last step's finalized slices never re-gathered

        dim3 gi(IMG_BLKS + (doFlow ? FLOW_BLKS : 0), Lp, Bc);
        compose_step<<<gi, 256>>>(s, finHWC, imgPar, flowSrc, flowDst, flows, out);

        imgPar ^= 1;
        flowSrc = flowDst;
    }
}

// round 16
// speedup vs baseline: 1.0500x; 1.0500x over previous
#include <cuda_runtime.h>
#include <cuda_fp16.h>
#include <math.h>

#define Bc 4
#define Lc 32
#define Cc 32
#define Hc 128
#define Wc 128
#define HWc (Hc*Wc)
#define IMG_SLICE (Cc*HWc)          // fp32 elements per image slice (d_out)
#define IMG_SLICE_H (Cc*HWc)        // fp16 elements per internal slice
#define IMG_BLKS (HWc/64)           // 256 image blocks per (lp,b), 64 px each
#define FLOW_BLKS (HWc/256)         // 64 flow blocks per (lp,b)

// Internal image buffers, channel-interleaved [B,L,H,W,C], fp16 (uint4 aligned).
__device__ uint4 g_imgA4[(size_t)Bc*Lc*IMG_SLICE_H/8];   // transposed input + ping-pong
__device__ uint4 g_imgB4[(size_t)Bc*Lc*IMG_SLICE_H/8];   // ping-pong
__device__ uint4 g_imgF4[(size_t)Bc*Lc*IMG_SLICE_H/8];   // finalized gather sources
// Flow buffers, planar [B,L,2,H,W], fp32 (precision-critical: feeds coordinates)
__device__ float g_flowA[(size_t)Bc*Lc*2*HWc];
__device__ float g_flowB[(size_t)Bc*Lc*2*HWc];
__device__ float g_flowF[(size_t)Bc*Lc*2*HWc];

union H8 { uint4 u; __half2 h[4]; };

// ---------------------------------------------------------------------------
// CHW(fp32) -> HWC(fp16) transpose of all input image slices into g_imgA;
// also copies slice l==0 straight to d_out (CHW fp32) on the fly.
__global__ void t_chw2hwc(const float* __restrict__ src, float* __restrict__ out) {
    __shared__ float sm[32][65];
    int tile = blockIdx.x & 255;
    int sl   = blockIdx.x >> 8;
    int pix0 = tile * 64;
    const float* s = src + (size_t)sl * IMG_SLICE;
    __half*      d = (__half*)g_imgA4 + (size_t)sl * IMG_SLICE_H;
    float*       o = out + (size_t)sl * IMG_SLICE;
    bool isL0 = ((sl & (Lc - 1)) == 0);
    int tx = threadIdx.x & 63, ty = threadIdx.x >> 6;
    #pragma unroll
    for (int i = 0; i < 8; i++) {
        int c = ty + i * 4;
        float v = s[c * HWc + pix0 + tx];
        sm[c][tx] = v;
        if (isL0) o[c * HWc + pix0 + tx] = v;
    }
    __syncthreads();
    // each thread packs 8 channels of one pixel into a uint4 (8 halves)
    int p = threadIdx.x >> 2, q = threadIdx.x & 3;
    H8 v;
    #pragma unroll
    for (int j = 0; j < 4; j++)
        v.h[j] = __floats2half2_rn(sm[8*q + 2*j][p], sm[8*q + 2*j + 1][p]);
    *(uint4*)(d + (pix0 + p) * Cc + q * 8) = v.u;
}

// ---------------------------------------------------------------------------
// Grid/weight computation — VERBATIM the numerics that passed (R2/R5/R10/R11).
__device__ __forceinline__ void grid_weights(
    int pix, float qfx, float qfy,
    float& w00, float& w01, float& w10, float& w11,
    int& o00, int& o01, int& o10, int& o11)
{
    int h = pix >> 7;
    int w = pix & (Wc - 1);
    float gx = -1.0f + (2.0f / Wc) * ((float)w + 0.5f);
    float gy = -1.0f + (2.0f / Hc) * ((float)h + 0.5f);
    float fx = gx + qfx;
    float t  = fx + 1.0f;
    fx = t - 2.0f * floorf(t * 0.5f) - 1.0f;   // remainder(fx+1,2)-1 (x wrap)
    float fy = gy + qfy;

    float x = (fx + 1.0f) * (Wc * 0.5f) - 0.5f;
    float y = (fy + 1.0f) * (Hc * 0.5f) - 0.5f;
    float x0f = floorf(x), y0f = floorf(y);
    float tx = x - x0f, ty = y - y0f;
    int x0 = (int)x0f, y0 = (int)y0f;
    int x1 = x0 + 1,  y1 = y0 + 1;

    float vx0 = (x0 >= 0 && x0 < Wc) ? 1.0f : 0.0f;
    float vx1 = (x1 >= 0 && x1 < Wc) ? 1.0f : 0.0f;
    float vy0 = (y0 >= 0 && y0 < Hc) ? 1.0f : 0.0f;
    float vy1 = (y1 >= 0 && y1 < Hc) ? 1.0f : 0.0f;

    w00 = (1.0f - tx) * (1.0f - ty) * vx0 * vy0;
    w01 = tx * (1.0f - ty) * vx1 * vy0;
    w10 = (1.0f - tx) * ty * vx0 * vy1;
    w11 = tx * ty * vx1 * vy1;

    int cx0 = min(max(x0, 0), Wc - 1), cx1 = min(max(x1, 0), Wc - 1);
    int cy0 = min(max(y0, 0), Hc - 1), cy1 = min(max(y1, 0), Hc - 1);
    o00 = cy0 * Wc + cx0; o01 = cy0 * Wc + cx1;
    o10 = cy1 * Wc + cx0; o11 = cy1 * Wc + cx1;
}

// flowSel: 0 = runtime input flows, 1 = g_flowA, 2 = g_flowB
__device__ __forceinline__ const float* flow_sel(int sel, const float* flows) {
    return (sel == 0) ? flows : (sel == 1) ? (const float*)g_flowA : (const float*)g_flowB;
}

// ---------------------------------------------------------------------------
// Fused step kernel. Block-level specialization:
//   blockIdx.x <  IMG_BLKS : image compose (fp16 scratch, fp32 math)
//   blockIdx.x >= IMG_BLKS : flow compose (fp32, unchanged)
__global__ void __launch_bounds__(256) compose_step(int step, int finHWC,
    int imgPar, int flowSrcSel, int flowDstSel,
    const float* __restrict__ flows, float* __restrict__ outImg)
{
    int lp = blockIdx.y;
    int b  = blockIdx.z;
    int l  = step + lp;
    const float* srcFlow = flow_sel(flowSrcSel, flows);

    if (blockIdx.x >= IMG_BLKS) {
        // ---------------- flow path (fp32, verbatim R10/R14) ----------------
        int pix = (blockIdx.x - IMG_BLKS) * 256 + threadIdx.x;

        const float* cf = srcFlow + (b * Lc + l) * (2 * HWc);
        float qfx = __ldg(cf + pix);
        float qfy = __ldg(cf + HWc + pix);

        float w00, w01, w10, w11; int o00, o01, o10, o11;
        grid_weights(pix, qfx, qfy, w00, w01, w10, w11, o00, o01, o10, o11);

        const float* pf = (lp == 0) ? (flows + (b * Lc) * (2 * HWc))
                       : (lp < step) ? ((const float*)g_flowF + (b * Lc + lp) * (2 * HWc))
                                     : (srcFlow + (b * Lc + lp) * (2 * HWc));
        float* dstFlow = (flowDstSel == 1) ? g_flowA : g_flowB;
        float* df = ((l < 2 * step) ? g_flowF : dstFlow) + (b * Lc + l) * (2 * HWc);

        float s0 = w00 * __ldg(pf + o00) + w01 * __ldg(pf + o01)
                 + w10 * __ldg(pf + o10) + w11 * __ldg(pf + o11);
        const float* pf1 = pf + HWc;
        float s1 = w00 * __ldg(pf1 + o00) + w01 * __ldg(pf1 + o01)
                 + w10 * __ldg(pf1 + o10) + w11 * __ldg(pf1 + o11);
        df[pix]       = qfx + s0;
        df[HWc + pix] = qfy + s1;
        return;
    }

    // ---------------- image path: warp = 8 px x 4 groups (8ch fp16/lane) ---
    // VERBATIM R14 body except finalized CHW stores go DIRECT to d_out:
    // lane (pl,c8) holds channels co..co+7 of pixel pl; per store instruction
    // warp covers 4 channel-planes x 8 consecutive px = 4 x 32B sectors.
    // No shared memory, no __syncthreads in this path.
    int t   = threadIdx.x;
    int c8  = t & 3;
    int pl  = t >> 2;                 // pixel-local 0..63
    int pix = blockIdx.x * 64 + pl;
    int co  = c8 * 8;                 // channel offset (halves)

    const __half* srcImg = (const __half*)(imgPar ? g_imgB4 : g_imgA4);
    __half*       dstImg = (__half*)(imgPar ? g_imgA4 : g_imgB4);

    const float* cf = srcFlow + (b * Lc + l) * (2 * HWc);
    float qfx = __ldg(cf + pix);
    float qfy = __ldg(cf + HWc + pix);

    float w00, w01, w10, w11; int o00, o01, o10, o11;
    grid_weights(pix, qfx, qfy, w00, w01, w10, w11, o00, o01, o10, o11);

    const __half* pi = ((lp == 0) ? (const __half*)g_imgA4
                      : (lp < step) ? (const __half*)g_imgF4 : srcImg)
                       + (b * Lc + lp) * IMG_SLICE_H;
    H8 t00, t01, t10, t11, cv8;
    t00.u = *(const uint4*)(pi + o00 * Cc + co);
    t01.u = *(const uint4*)(pi + o01 * Cc + co);
    t10.u = *(const uint4*)(pi + o10 * Cc + co);
    t11.u = *(const uint4*)(pi + o11 * Cc + co);

    int hwcOff = (b * Lc + l) * IMG_SLICE_H + pix * Cc + co;
    cv8.u = *(const uint4*)(srcImg + hwcOff);

    float r[8];
    #pragma unroll
    for (int k = 0; k < 4; k++) {
        float2 c  = __half22float2(cv8.h[k]);
        float2 a0 = __half22float2(t00.h[k]);
        float2 a1 = __half22float2(t01.h[k]);
        float2 a2 = __half22float2(t10.h[k]);
        float2 a3 = __half22float2(t11.h[k]);
        r[2*k]   = c.x + w00 * a0.x + w01 * a1.x + w10 * a2.x + w11 * a3.x;
        r[2*k+1] = c.y + w00 * a0.y + w01 * a1.y + w10 * a2.y + w11 * a3.y;
    }

    if (l < 2 * step) {                         // finalized (block-uniform)
        if (finHWC) {
            H8 ov;
            #pragma unroll
            for (int k = 0; k < 4; k++)
                ov.h[k] = __floats2half2_rn(r[2*k], r[2*k+1]);
            *(uint4*)((__half*)g_imgF4 + hwcOff) = ov.u;
        }
        // direct CHW stores: per instr 4 ch-planes x 8 contiguous px = 4x32B sectors
        float* oC = outImg + (b * Lc + l) * IMG_SLICE + pix;
        #pragma unroll
        for (int i = 0; i < 8; i++)
            __stcs(oC + (co + i) * HWc, r[i]);
    } else {
        H8 ov;
        #pragma unroll
        for (int k = 0; k < 4; k++)
            ov.h[k] = __floats2half2_rn(r[2*k], r[2*k+1]);
        *(uint4*)(dstImg + hwcOff) = ov.u;
    }
}

// ---------------------------------------------------------------------------
extern "C" void kernel_launch(void* const* d_in, const int* in_sizes, int n_in,
                              void* d_out, int out_size) {
    const float* flows  = (const float*)d_in[0];
    const float* images = (const float*)d_in[1];
    if (n_in >= 2 && in_sizes[0] > in_sizes[1]) {
        const float* tmp = flows; flows = images; images = tmp;
    }
    float* out = (float*)d_out;

    // 1) transpose input images CHW(fp32) -> HWC(fp16) into g_imgA (+ slice0 -> d_out)
    t_chw2hwc<<<Bc * Lc * 256, 256>>>(images, out);

    // 2) log-scan, one fused launch per step (image blocks + flow blocks).
    int imgPar = 0;
    int flowSrc = 0;
    for (int s = 1; s < Lc; s <<= 1) {
        int Lp = Lc - s;
        int flowDst = (flowSrc == 2) ? 1 : 2;
        int doFlow = (s < 16) ? 1 : 0;   // last step's flow output never consumed
        int finHWC = (s < 16) ? 1 : 0;   // last step's finalized slices never re-gathered

        dim3 gi(IMG_BLKS + (doFlow ? FLOW_BLKS : 0), Lp, Bc);
        compose_step<<<gi, 256>>>(s, finHWC, imgPar, flowSrc, flowDst, flows, out);

        imgPar ^= 1;
        flowSrc = flowDst;
    }
}

// round 17
// speedup vs baseline: 1.0616x; 1.0110x over previous
#include <cuda_runtime.h>
#include <cuda_fp16.h>
#include <math.h>

#define Bc 4
#define Lc 32
#define Cc 32
#define Hc 128
#define Wc 128
#define HWc (Hc*Wc)
#define IMG_SLICE (Cc*HWc)          // fp32 elements per image slice (d_out)
#define IMG_SLICE_H (Cc*HWc)        // fp16 elements per internal slice
#define IMG_BLKS (HWc/64)           // 256 image blocks per (lp,b), 64 px each
#define FLOW_BLKS (HWc/256)         // 64 flow blocks per (lp,b)

// Internal image buffers, channel-interleaved [B,L,H,W,C], fp16 (uint4 aligned).
__device__ uint4 g_imgA4[(size_t)Bc*Lc*IMG_SLICE_H/8];   // transposed input + ping-pong
__device__ uint4 g_imgB4[(size_t)Bc*Lc*IMG_SLICE_H/8];   // ping-pong
__device__ uint4 g_imgF4[(size_t)Bc*Lc*IMG_SLICE_H/8];   // finalized gather sources
// Internal flow buffers, INTERLEAVED [B,L,H,W,2] fp32 (one float2 per pixel).
__device__ float2 g_flowA2[(size_t)Bc*Lc*HWc];
__device__ float2 g_flowB2[(size_t)Bc*Lc*HWc];
__device__ float2 g_flowF2[(size_t)Bc*Lc*HWc];

union H8 { uint4 u; __half2 h[4]; };

// ---------------------------------------------------------------------------
// CHW(fp32) -> HWC(fp16) transpose of all input image slices into g_imgA;
// also copies slice l==0 straight to d_out (CHW fp32) on the fly.
__global__ void t_chw2hwc(const float* __restrict__ src, float* __restrict__ out) {
    __shared__ float sm[32][65];
    int tile = blockIdx.x & 255;
    int sl   = blockIdx.x >> 8;
    int pix0 = tile * 64;
    const float* s = src + (size_t)sl * IMG_SLICE;
    __half*      d = (__half*)g_imgA4 + (size_t)sl * IMG_SLICE_H;
    float*       o = out + (size_t)sl * IMG_SLICE;
    bool isL0 = ((sl & (Lc - 1)) == 0);
    int tx = threadIdx.x & 63, ty = threadIdx.x >> 6;
    #pragma unroll
    for (int i = 0; i < 8; i++) {
        int c = ty + i * 4;
        float v = s[c * HWc + pix0 + tx];
        sm[c][tx] = v;
        if (isL0) o[c * HWc + pix0 + tx] = v;
    }
    __syncthreads();
    // each thread packs 8 channels of one pixel into a uint4 (8 halves)
    int p = threadIdx.x >> 2, q = threadIdx.x & 3;
    H8 v;
    #pragma unroll
    for (int j = 0; j < 4; j++)
        v.h[j] = __floats2half2_rn(sm[8*q + 2*j][p], sm[8*q + 2*j + 1][p]);
    *(uint4*)(d + (pix0 + p) * Cc + q * 8) = v.u;
}

// ---------------------------------------------------------------------------
// Grid/weight computation — VERBATIM the numerics that passed (R2/R5/R10/R11).
__device__ __forceinline__ void grid_weights(
    int pix, float qfx, float qfy,
    float& w00, float& w01, float& w10, float& w11,
    int& o00, int& o01, int& o10, int& o11)
{
    int h = pix >> 7;
    int w = pix & (Wc - 1);
    float gx = -1.0f + (2.0f / Wc) * ((float)w + 0.5f);
    float gy = -1.0f + (2.0f / Hc) * ((float)h + 0.5f);
    float fx = gx + qfx;
    float t  = fx + 1.0f;
    fx = t - 2.0f * floorf(t * 0.5f) - 1.0f;   // remainder(fx+1,2)-1 (x wrap)
    float fy = gy + qfy;

    float x = (fx + 1.0f) * (Wc * 0.5f) - 0.5f;
    float y = (fy + 1.0f) * (Hc * 0.5f) - 0.5f;
    float x0f = floorf(x), y0f = floorf(y);
    float tx = x - x0f, ty = y - y0f;
    int x0 = (int)x0f, y0 = (int)y0f;
    int x1 = x0 + 1,  y1 = y0 + 1;

    float vx0 = (x0 >= 0 && x0 < Wc) ? 1.0f : 0.0f;
    float vx1 = (x1 >= 0 && x1 < Wc) ? 1.0f : 0.0f;
    float vy0 = (y0 >= 0 && y0 < Hc) ? 1.0f : 0.0f;
    float vy1 = (y1 >= 0 && y1 < Hc) ? 1.0f : 0.0f;

    w00 = (1.0f - tx) * (1.0f - ty) * vx0 * vy0;
    w01 = tx * (1.0f - ty) * vx1 * vy0;
    w10 = (1.0f - tx) * ty * vx0 * vy1;
    w11 = tx * ty * vx1 * vy1;

    int cx0 = min(max(x0, 0), Wc - 1), cx1 = min(max(x1, 0), Wc - 1);
    int cy0 = min(max(y0, 0), Hc - 1), cy1 = min(max(y1, 0), Hc - 1);
    o00 = cy0 * Wc + cx0; o01 = cy0 * Wc + cx1;
    o10 = cy1 * Wc + cx0; o11 = cy1 * Wc + cx1;
}

// flowSel for interleaved internal buffers: 1 = g_flowA2, else g_flowB2
__device__ __forceinline__ const float2* flow_sel2(int sel) {
    return (sel == 1) ? (const float2*)g_flowA2 : (const float2*)g_flowB2;
}

// ---------------------------------------------------------------------------
// Fused step kernel. Block-level specialization:
//   blockIdx.x <  IMG_BLKS : image compose (fp16 scratch, fp32 math)
//   blockIdx.x >= IMG_BLKS : flow compose (fp32, interleaved internal storage)
__global__ void __launch_bounds__(256) compose_step(int step, int finHWC,
    int imgPar, int flowSrcSel, int flowDstSel,
    const float* __restrict__ flows, float* __restrict__ outImg)
{
    int lp = blockIdx.y;
    int b  = blockIdx.z;
    int l  = step + lp;

    if (blockIdx.x >= IMG_BLKS) {
        // ---------------- flow path ----------------
        int pix = (blockIdx.x - IMG_BLKS) * 256 + threadIdx.x;

        // curr flow (slice l >= step): planar input at step 1, else interleaved
        float qfx, qfy;
        if (flowSrcSel == 0) {
            const float* cf = flows + (b * Lc + l) * (2 * HWc);
            qfx = __ldg(cf + pix);
            qfy = __ldg(cf + HWc + pix);
        } else {
            float2 q = __ldg(flow_sel2(flowSrcSel) + (b * Lc + l) * HWc + pix);
            qfx = q.x; qfy = q.y;
        }

        float w00, w01, w10, w11; int o00, o01, o10, o11;
        grid_weights(pix, qfx, qfy, w00, w01, w10, w11, o00, o01, o10, o11);

        float s0, s1;
        if (lp == 0 || flowSrcSel == 0) {
            // planar source: original input flows, slice lp
            const float* pf = flows + (b * Lc + lp) * (2 * HWc);
            s0 = w00 * __ldg(pf + o00) + w01 * __ldg(pf + o01)
               + w10 * __ldg(pf + o10) + w11 * __ldg(pf + o11);
            const float* pf1 = pf + HWc;
            s1 = w00 * __ldg(pf1 + o00) + w01 * __ldg(pf1 + o01)
               + w10 * __ldg(pf1 + o10) + w11 * __ldg(pf1 + o11);
        } else {
            const float2* pf2 = ((lp < step) ? (const float2*)g_flowF2
                                             : flow_sel2(flowSrcSel))
                                + (b * Lc + lp) * HWc;
            float2 v00 = __ldg(pf2 + o00);
            float2 v01 = __ldg(pf2 + o01);
            float2 v10 = __ldg(pf2 + o10);
            float2 v11 = __ldg(pf2 + o11);
            s0 = w00 * v00.x + w01 * v01.x + w10 * v10.x + w11 * v11.x;
            s1 = w00 * v00.y + w01 * v01.y + w10 * v10.y + w11 * v11.y;
        }

        float2* dstF2 = (flowDstSel == 1) ? g_flowA2 : g_flowB2;
        float2* df2 = ((l < 2 * step) ? g_flowF2 : dstF2) + (b * Lc + l) * HWc;
        df2[pix] = make_float2(qfx + s0, qfy + s1);
        return;
    }

    // ---------------- image path: warp = 8 px x 4 groups (8ch fp16/lane) ---
    // VERBATIM R16 body; only the curr-flow read differs (interleaved when
    // flowSrcSel != 0 — block-uniform branch).
    int t   = threadIdx.x;
    int c8  = t & 3;
    int pl  = t >> 2;                 // pixel-local 0..63
    int pix = blockIdx.x * 64 + pl;
    int co  = c8 * 8;                 // channel offset (halves)

    const __half* srcImg = (const __half*)(imgPar ? g_imgB4 : g_imgA4);
    __half*       dstImg = (__half*)(imgPar ? g_imgA4 : g_imgB4);

    float qfx, qfy;
    if (flowSrcSel == 0) {
        const float* cf = flows + (b * Lc + l) * (2 * HWc);
        qfx = __ldg(cf + pix);
        qfy = __ldg(cf + HWc + pix);
    } else {
        float2 q = __ldg(flow_sel2(flowSrcSel) + (b * Lc + l) * HWc + pix);
        qfx = q.x; qfy = q.y;
    }

    float w00, w01, w10, w11; int o00, o01, o10, o11;
    grid_weights(pix, qfx, qfy, w00, w01, w10, w11, o00, o01, o10, o11);

    const __half* pi = ((lp == 0) ? (const __half*)g_imgA4
                      : (lp < step) ? (const __half*)g_imgF4 : srcImg)
                       + (b * Lc + lp) * IMG_SLICE_H;
    H8 t00, t01, t10, t11, cv8;
    t00.u = *(const uint4*)(pi + o00 * Cc + co);
    t01.u = *(const uint4*)(pi + o01 * Cc + co);
    t10.u = *(const uint4*)(pi + o10 * Cc + co);
    t11.u = *(const uint4*)(pi + o11 * Cc + co);

    int hwcOff = (b * Lc + l) * IMG_SLICE_H + pix * Cc + co;
    cv8.u = *(const uint4*)(srcImg + hwcOff);

    float r[8];
    #pragma unroll
    for (int k = 0; k < 4; k++) {
        float2 c  = __half22float2(cv8.h[k]);
        float2 a0 = __half22float2(t00.h[k]);
        float2 a1 = __half22float2(t01.h[k]);
        float2 a2 = __half22float2(t10.h[k]);
        float2 a3 = __half22float2(t11.h[k]);
        r[2*k]   = c.x + w00 * a0.x + w01 * a1.x + w10 * a2.x + w11 * a3.x;
        r[2*k+1] = c.y + w00 * a0.y + w01 * a1.y + w10 * a2.y + w11 * a3.y;
    }

    if (l < 2 * step) {                         // finalized (block-uniform)
        if (finHWC) {
            H8 ov;
            #pragma unroll
            for (int k = 0; k < 4; k++)
                ov.h[k] = __floats2half2_rn(r[2*k], r[2*k+1]);
            *(uint4*)((__half*)g_imgF4 + hwcOff) = ov.u;
        }
        // direct CHW stores: per instr 4 ch-planes x 8 contiguous px = 4x32B sectors
        float* oC = outImg + (b * Lc + l) * IMG_SLICE + pix;
        #pragma unroll
        for (int i = 0; i < 8; i++)
            __stcs(oC + (co + i) * HWc, r[i]);
    } else {
        H8 ov;
        #pragma unroll
        for (int k = 0; k < 4; k++)
            ov.h[k] = __floats2half2_rn(r[2*k], r[2*k+1]);
        *(uint4*)(dstImg + hwcOff) = ov.u;
    }
}

// ---------------------------------------------------------------------------
extern "C" void kernel_launch(void* const* d_in, const int* in_sizes, int n_in,
                              void* d_out, int out_size) {
    const float* flows  = (const float*)d_in[0];
    const float* images = (const float*)d_in[1];
    if (n_in >= 2 && in_sizes[0] > in_sizes[1]) {
        const float* tmp = flows; flows = images; images = tmp;
    }
    float* out = (float*)d_out;

    // 1) transpose input images CHW(fp32) -> HWC(fp16) into g_imgA (+ slice0 -> d_out)
    t_chw2hwc<<<Bc * Lc * 256, 256>>>(images, out);

    // 2) log-scan, one fused launch per step (image blocks + flow blocks).
    int imgPar = 0;
    int flowSrc = 0;
    for (int s = 1; s < Lc; s <<= 1) {
        int Lp = Lc - s;
        int flowDst = (flowSrc == 2) ? 1 : 2;
        int doFlow = (s < 16) ? 1 : 0;   // last step's flow output never consumed
        int finHWC = (s < 16) ? 1 : 0;   // last step's finalized slices never re-gathered

        dim3 gi(IMG_BLKS + (doFlow ? FLOW_BLKS : 0), Lp, Bc);
        compose_step<<<gi, 256>>>(s, finHWC, imgPar, flowSrc, flowDst, flows, out);

        imgPar ^= 1;
        flowSrc = flowDst;
    }
}